// round 1
// baseline (speedup 1.0000x reference)
#include <cuda_runtime.h>
#include <math.h>

// Problem constants (fixed by setup_inputs)
#define DMODEL 1024
#define NHEADS 16
#define DKH    64
#define SEQ    2048
#define BATCH  2
#define MROWS  (BATCH*SEQ)   // 4096
#define DFF    4096

// ---------------- scratch (device globals: allocation-guard safe) ----------
__device__ float g_h [MROWS*DMODEL];   // LN output (reused for LN2)
__device__ float g_q [MROWS*DMODEL];
__device__ float g_k [MROWS*DMODEL];
__device__ float g_v [MROWS*DMODEL];
__device__ float g_a [MROWS*DMODEL];   // attention output
__device__ float g_x2[MROWS*DMODEL];   // residual after attention
__device__ float g_f1[MROWS*DFF];      // FFN hidden

// ---------------- LayerNorm: one block per row, 256 threads ----------------
__global__ __launch_bounds__(256) void layernorm_k(
    const float* __restrict__ x, const float* __restrict__ gamma,
    const float* __restrict__ beta, float* __restrict__ out)
{
    int row = blockIdx.x;
    int tid = threadIdx.x;
    const float4* xr = (const float4*)(x + (size_t)row * DMODEL);
    float4 v = xr[tid];
    float s  = v.x + v.y + v.z + v.w;
    float ss = v.x*v.x + v.y*v.y + v.z*v.z + v.w*v.w;
    #pragma unroll
    for (int o = 16; o > 0; o >>= 1) {
        s  += __shfl_xor_sync(0xffffffffu, s,  o);
        ss += __shfl_xor_sync(0xffffffffu, ss, o);
    }
    __shared__ float sred[8], ssred[8];
    int w = tid >> 5;
    if ((tid & 31) == 0) { sred[w] = s; ssred[w] = ss; }
    __syncthreads();
    float tot = 0.f, tot2 = 0.f;
    #pragma unroll
    for (int i = 0; i < 8; i++) { tot += sred[i]; tot2 += ssred[i]; }
    float mu  = tot  * (1.0f / DMODEL);
    float var = tot2 * (1.0f / DMODEL) - mu * mu;
    float inv = rsqrtf(var + 1e-5f);
    float4 gg = ((const float4*)gamma)[tid];
    float4 bb = ((const float4*)beta)[tid];
    float4 o;
    o.x = (v.x - mu) * inv * gg.x + bb.x;
    o.y = (v.y - mu) * inv * gg.y + bb.y;
    o.z = (v.z - mu) * inv * gg.z + bb.z;
    o.w = (v.w - mu) * inv * gg.w + bb.w;
    ((float4*)(out + (size_t)row * DMODEL))[tid] = o;
}

// ---------------- NT GEMM: C[M,N] = A[M,K] * B[N,K]^T (+bias,+relu,+res) ---
// 128x128 block tile, BK=16, 256 threads, split 2x(4x4) micro-tiles.
// RELU applies BEFORE residual add (matches reference: relu(h@W2^T+b2)+res).
template<bool RELU, bool RES>
__global__ __launch_bounds__(256) void gemm_nt(
    const float* __restrict__ A, const float* __restrict__ B,
    const float* __restrict__ bias, const float* __restrict__ res,
    float* __restrict__ C, int M, int N, int K)
{
    __shared__ float As[16][128];
    __shared__ float Bs[16][128];
    int t  = threadIdx.x;
    int tx = t & 15, ty = t >> 4;
    int bm = blockIdx.y * 128, bn = blockIdx.x * 128;
    int lr = t >> 2;            // 0..63
    int lc = (t & 3) << 2;      // 0,4,8,12
    const float* Aptr = A + (size_t)(bm + lr) * K + lc;
    const float* Bptr = B + (size_t)(bn + lr) * K + lc;

    float acc[8][8];
    #pragma unroll
    for (int i = 0; i < 8; i++)
        #pragma unroll
        for (int j = 0; j < 8; j++) acc[i][j] = 0.f;

    for (int k0 = 0; k0 < K; k0 += 16) {
        float4 a0 = *(const float4*)(Aptr);
        float4 a1 = *(const float4*)(Aptr + (size_t)64 * K);
        float4 b0 = *(const float4*)(Bptr);
        float4 b1 = *(const float4*)(Bptr + (size_t)64 * K);
        As[lc+0][lr] = a0.x; As[lc+1][lr] = a0.y; As[lc+2][lr] = a0.z; As[lc+3][lr] = a0.w;
        As[lc+0][lr+64] = a1.x; As[lc+1][lr+64] = a1.y; As[lc+2][lr+64] = a1.z; As[lc+3][lr+64] = a1.w;
        Bs[lc+0][lr] = b0.x; Bs[lc+1][lr] = b0.y; Bs[lc+2][lr] = b0.z; Bs[lc+3][lr] = b0.w;
        Bs[lc+0][lr+64] = b1.x; Bs[lc+1][lr+64] = b1.y; Bs[lc+2][lr+64] = b1.z; Bs[lc+3][lr+64] = b1.w;
        __syncthreads();
        #pragma unroll
        for (int k = 0; k < 16; k++) {
            float4 ra0 = *(const float4*)&As[k][ty*4];
            float4 ra1 = *(const float4*)&As[k][64 + ty*4];
            float4 rb0 = *(const float4*)&Bs[k][tx*4];
            float4 rb1 = *(const float4*)&Bs[k][64 + tx*4];
            float ra[8] = {ra0.x, ra0.y, ra0.z, ra0.w, ra1.x, ra1.y, ra1.z, ra1.w};
            float rb[8] = {rb0.x, rb0.y, rb0.z, rb0.w, rb1.x, rb1.y, rb1.z, rb1.w};
            #pragma unroll
            for (int i = 0; i < 8; i++)
                #pragma unroll
                for (int j = 0; j < 8; j++)
                    acc[i][j] += ra[i] * rb[j];
        }
        __syncthreads();
        Aptr += 16; Bptr += 16;
    }

    float bv[8];
    if (bias) {
        float4 c0 = *(const float4*)(bias + bn + tx*4);
        float4 c1 = *(const float4*)(bias + bn + 64 + tx*4);
        bv[0]=c0.x; bv[1]=c0.y; bv[2]=c0.z; bv[3]=c0.w;
        bv[4]=c1.x; bv[5]=c1.y; bv[6]=c1.z; bv[7]=c1.w;
    } else {
        #pragma unroll
        for (int j = 0; j < 8; j++) bv[j] = 0.f;
    }

    #pragma unroll
    for (int i = 0; i < 8; i++) {
        int r = bm + ((i < 4) ? (ty*4 + i) : (64 + ty*4 + i - 4));
        float* Crow = C + (size_t)r * N + bn;
        float o[8];
        #pragma unroll
        for (int j = 0; j < 8; j++) {
            float vv = acc[i][j] + bv[j];
            if (RELU) vv = fmaxf(vv, 0.f);
            o[j] = vv;
        }
        if (RES) {
            const float* Rrow = res + (size_t)r * N + bn;
            float4 r0 = *(const float4*)(Rrow + tx*4);
            float4 r1 = *(const float4*)(Rrow + 64 + tx*4);
            o[0]+=r0.x; o[1]+=r0.y; o[2]+=r0.z; o[3]+=r0.w;
            o[4]+=r1.x; o[5]+=r1.y; o[6]+=r1.z; o[7]+=r1.w;
        }
        float4 s0 = {o[0], o[1], o[2], o[3]};
        float4 s1 = {o[4], o[5], o[6], o[7]};
        *(float4*)(Crow + tx*4) = s0;
        *(float4*)(Crow + 64 + tx*4) = s1;
    }
}

// ---------------- Flash attention: 64q x 64kv tiles, dk=64 -----------------
// grid = (SEQ/64, BATCH*NHEADS), 256 threads (16x16), each thread 4x4.
// smem: Qt[d][q], KPs (Kt[d][key] reused as Ps[q][c]), Vs[key][d] = 48KB.
__global__ __launch_bounds__(256) void attn_k(
    const float* __restrict__ Q, const float* __restrict__ K,
    const float* __restrict__ V, const unsigned char* __restrict__ mask,
    float* __restrict__ O)
{
    __shared__ float Qt [64][64];
    __shared__ float KPs[64][64];
    __shared__ float Vs [64][64];
    int t  = threadIdx.x;
    int tx = t & 15, ty = t >> 4;
    int bh = blockIdx.y;
    int b = bh >> 4, h = bh & 15;
    int q0 = blockIdx.x * 64;
    size_t baseQ  = ((size_t)(b*SEQ + q0)) * DMODEL + h*DKH;
    size_t baseKV = ((size_t)(b*SEQ)) * DMODEL + h*DKH;
    const unsigned char* mrow = mask + (size_t)b * SEQ;

    // Load Q tile transposed: Qt[d][q]
    {
        int r = t >> 2;               // q index 0..63
        int dbase = (t & 3) << 4;     // 0,16,32,48
        const float* qp = Q + baseQ + (size_t)r * DMODEL + dbase;
        #pragma unroll
        for (int i = 0; i < 4; i++) {
            float4 qv = *(const float4*)(qp + i*4);
            Qt[dbase+i*4+0][r] = qv.x; Qt[dbase+i*4+1][r] = qv.y;
            Qt[dbase+i*4+2][r] = qv.z; Qt[dbase+i*4+3][r] = qv.w;
        }
    }

    float m_[4], l_[4], o_[4][4];
    #pragma unroll
    for (int i = 0; i < 4; i++) {
        m_[i] = -INFINITY; l_[i] = 0.f;
        #pragma unroll
        for (int j = 0; j < 4; j++) o_[i][j] = 0.f;
    }

    for (int kv0 = 0; kv0 < SEQ; kv0 += 64) {
        __syncthreads();   // previous iteration's PV reads of KPs/Vs done
        // Load K transposed -> KPs[d][key], V natural -> Vs[key][d]
        {
            int r = t >> 2;
            int dbase = (t & 3) << 4;
            const float* kp = K + baseKV + (size_t)(kv0 + r) * DMODEL + dbase;
            const float* vp = V + baseKV + (size_t)(kv0 + r) * DMODEL + dbase;
            #pragma unroll
            for (int i = 0; i < 4; i++) {
                float4 kv = *(const float4*)(kp + i*4);
                KPs[dbase+i*4+0][r] = kv.x; KPs[dbase+i*4+1][r] = kv.y;
                KPs[dbase+i*4+2][r] = kv.z; KPs[dbase+i*4+3][r] = kv.w;
                float4 vv = *(const float4*)(vp + i*4);
                *(float4*)&Vs[r][dbase+i*4] = vv;
            }
        }
        __syncthreads();

        // S = Q K^T
        float s[4][4];
        #pragma unroll
        for (int i = 0; i < 4; i++)
            #pragma unroll
            for (int j = 0; j < 4; j++) s[i][j] = 0.f;
        #pragma unroll 8
        for (int d = 0; d < 64; d++) {
            float4 qv = *(const float4*)&Qt[d][ty*4];     // broadcast
            float4 kv = *(const float4*)&KPs[d][tx*4];    // conflict-free
            float qa[4] = {qv.x, qv.y, qv.z, qv.w};
            float ka[4] = {kv.x, kv.y, kv.z, kv.w};
            #pragma unroll
            for (int i = 0; i < 4; i++)
                #pragma unroll
                for (int j = 0; j < 4; j++)
                    s[i][j] += qa[i] * ka[j];
        }
        // scale + mask
        #pragma unroll
        for (int j = 0; j < 4; j++) {
            unsigned char mk = mrow[kv0 + tx*4 + j];
            #pragma unroll
            for (int i = 0; i < 4; i++)
                s[i][j] = mk ? -1e30f : s[i][j] * 0.125f;
        }
        // online softmax (row stats across the 16-lane half-warp group)
        float p[4][4];
        #pragma unroll
        for (int i = 0; i < 4; i++) {
            float rm = fmaxf(fmaxf(s[i][0], s[i][1]), fmaxf(s[i][2], s[i][3]));
            #pragma unroll
            for (int off = 8; off >= 1; off >>= 1)
                rm = fmaxf(rm, __shfl_xor_sync(0xffffffffu, rm, off));
            float mn = fmaxf(m_[i], rm);
            float corr = __expf(m_[i] - mn);
            m_[i] = mn;
            float rs = 0.f;
            #pragma unroll
            for (int j = 0; j < 4; j++) {
                p[i][j] = __expf(s[i][j] - mn);
                rs += p[i][j];
            }
            #pragma unroll
            for (int off = 8; off >= 1; off >>= 1)
                rs += __shfl_xor_sync(0xffffffffu, rs, off);
            l_[i] = l_[i] * corr + rs;
            #pragma unroll
            for (int j = 0; j < 4; j++) o_[i][j] *= corr;
        }
        __syncthreads();   // all S reads of KPs (as Kt) done
        // write P -> KPs[q][c]
        #pragma unroll
        for (int i = 0; i < 4; i++)
            #pragma unroll
            for (int j = 0; j < 4; j++)
                KPs[ty*4 + i][tx*4 + j] = p[i][j];
        __syncthreads();
        // O += P V
        #pragma unroll 4
        for (int c4 = 0; c4 < 16; c4++) {
            float pr[4][4];
            #pragma unroll
            for (int i = 0; i < 4; i++)
                *(float4*)&pr[i][0] = *(const float4*)&KPs[ty*4 + i][c4*4];  // broadcast
            #pragma unroll
            for (int mcl = 0; mcl < 4; mcl++) {
                float4 vv = *(const float4*)&Vs[c4*4 + mcl][tx*4];           // conflict-free
                float va[4] = {vv.x, vv.y, vv.z, vv.w};
                #pragma unroll
                for (int i = 0; i < 4; i++)
                    #pragma unroll
                    for (int j = 0; j < 4; j++)
                        o_[i][j] += pr[i][mcl] * va[j];
            }
        }
    }

    // write output: O[b, q, h*64 + d]
    #pragma unroll
    for (int i = 0; i < 4; i++) {
        float invl = 1.f / l_[i];
        float4 ov = {o_[i][0]*invl, o_[i][1]*invl, o_[i][2]*invl, o_[i][3]*invl};
        float* op = O + ((size_t)(b*SEQ + q0 + ty*4 + i)) * DMODEL + h*DKH + tx*4;
        *(float4*)op = ov;
    }
}

// ---------------- driver -----------------------------------------------------
static float* sym_addr(const void* sym) {
    void* p = nullptr;
    cudaGetSymbolAddress(&p, sym);
    return (float*)p;
}

extern "C" void kernel_launch(void* const* d_in, const int* in_sizes, int n_in,
                              void* d_out, int out_size)
{
    const float*         x     = (const float*)d_in[0];
    const unsigned char* mask  = (const unsigned char*)d_in[1];
    const float*         W_Q   = (const float*)d_in[2];
    const float*         W_K   = (const float*)d_in[3];
    const float*         W_V   = (const float*)d_in[4];
    const float*         W_O   = (const float*)d_in[5];
    const float*         W1    = (const float*)d_in[6];
    const float*         b1    = (const float*)d_in[7];
    const float*         W2    = (const float*)d_in[8];
    const float*         b2    = (const float*)d_in[9];
    const float*         g1    = (const float*)d_in[10];
    const float*         beta1 = (const float*)d_in[11];
    const float*         g2    = (const float*)d_in[12];
    const float*         beta2 = (const float*)d_in[13];
    float* out = (float*)d_out;

    float* h  = sym_addr(g_h);
    float* q  = sym_addr(g_q);
    float* k  = sym_addr(g_k);
    float* v  = sym_addr(g_v);
    float* a  = sym_addr(g_a);
    float* x2 = sym_addr(g_x2);
    float* f1 = sym_addr(g_f1);

    const int M = MROWS;
    dim3 blk(256);
    dim3 gD (DMODEL/128, M/128);   // N=1024
    dim3 gF (DFF/128,    M/128);   // N=4096

    // 1. LN1
    layernorm_k<<<M, blk>>>(x, g1, beta1, h);
    // 2. QKV projections
    gemm_nt<false,false><<<gD, blk>>>(h, W_Q, nullptr, nullptr, q, M, DMODEL, DMODEL);
    gemm_nt<false,false><<<gD, blk>>>(h, W_K, nullptr, nullptr, k, M, DMODEL, DMODEL);
    gemm_nt<false,false><<<gD, blk>>>(h, W_V, nullptr, nullptr, v, M, DMODEL, DMODEL);
    // 3. Attention
    attn_k<<<dim3(SEQ/64, BATCH*NHEADS), blk>>>(q, k, v, mask, a);
    // 4. O projection + residual
    gemm_nt<false,true><<<gD, blk>>>(a, W_O, nullptr, x, x2, M, DMODEL, DMODEL);
    // 5. LN2
    layernorm_k<<<M, blk>>>(x2, g2, beta2, h);
    // 6. FFN1 (+bias)
    gemm_nt<false,false><<<gF, blk>>>(h, W1, b1, nullptr, f1, M, DFF, DMODEL);
    // 7. FFN2 (+bias, relu-then-residual)
    gemm_nt<true,true><<<gD, blk>>>(f1, W2, b2, x2, out, M, DMODEL, DFF);
}

// round 2
// speedup vs baseline: 1.8537x; 1.8537x over previous
#include <cuda_runtime.h>
#include <math.h>
#include <stdint.h>

// Problem constants (fixed by setup_inputs)
#define DMODEL 1024
#define NHEADS 16
#define DKH    64
#define SEQ    2048
#define BATCH  2
#define MROWS  (BATCH*SEQ)   // 4096
#define DFF    4096

// ---------------- scratch (device globals: allocation-guard safe) ----------
__device__ float g_h [MROWS*DMODEL];   // LN output (reused for LN2)
__device__ float g_q [MROWS*DMODEL];
__device__ float g_k [MROWS*DMODEL];
__device__ float g_v [MROWS*DMODEL];
__device__ float g_a [MROWS*DMODEL];   // attention output
__device__ float g_x2[MROWS*DMODEL];   // residual after attention
__device__ float g_f1[MROWS*DFF];      // FFN hidden

// ---------------- PTX helpers ----------------------------------------------
__device__ __forceinline__ uint32_t f2tf(float f) {
    uint32_t u;
    asm("cvt.rna.tf32.f32 %0, %1;" : "=r"(u) : "f"(f));
    return u;
}
__device__ __forceinline__ void ldsm4(uint32_t r[4], uint32_t addr) {
    asm volatile("ldmatrix.sync.aligned.m8n8.x4.shared.b16 {%0,%1,%2,%3}, [%4];"
                 : "=r"(r[0]), "=r"(r[1]), "=r"(r[2]), "=r"(r[3]) : "r"(addr));
}
__device__ __forceinline__ void mma_tf32(float c[4], const uint32_t a[4], const uint32_t b0, const uint32_t b1) {
    asm volatile("mma.sync.aligned.m16n8k8.row.col.f32.tf32.tf32.f32 "
                 "{%0,%1,%2,%3}, {%4,%5,%6,%7}, {%8,%9}, {%0,%1,%2,%3};"
                 : "+f"(c[0]), "+f"(c[1]), "+f"(c[2]), "+f"(c[3])
                 : "r"(a[0]), "r"(a[1]), "r"(a[2]), "r"(a[3]), "r"(b0), "r"(b1));
}

// ---------------- LayerNorm: one block per row, 256 threads ----------------
__global__ __launch_bounds__(256) void layernorm_k(
    const float* __restrict__ x, const float* __restrict__ gamma,
    const float* __restrict__ beta, float* __restrict__ out)
{
    int row = blockIdx.x;
    int tid = threadIdx.x;
    const float4* xr = (const float4*)(x + (size_t)row * DMODEL);
    float4 v = xr[tid];
    float s  = v.x + v.y + v.z + v.w;
    float ss = v.x*v.x + v.y*v.y + v.z*v.z + v.w*v.w;
    #pragma unroll
    for (int o = 16; o > 0; o >>= 1) {
        s  += __shfl_xor_sync(0xffffffffu, s,  o);
        ss += __shfl_xor_sync(0xffffffffu, ss, o);
    }
    __shared__ float sred[8], ssred[8];
    int w = tid >> 5;
    if ((tid & 31) == 0) { sred[w] = s; ssred[w] = ss; }
    __syncthreads();
    float tot = 0.f, tot2 = 0.f;
    #pragma unroll
    for (int i = 0; i < 8; i++) { tot += sred[i]; tot2 += ssred[i]; }
    float mu  = tot  * (1.0f / DMODEL);
    float var = tot2 * (1.0f / DMODEL) - mu * mu;
    float inv = rsqrtf(var + 1e-5f);
    float4 gg = ((const float4*)gamma)[tid];
    float4 bb = ((const float4*)beta)[tid];
    float4 o;
    o.x = (v.x - mu) * inv * gg.x + bb.x;
    o.y = (v.y - mu) * inv * gg.y + bb.y;
    o.z = (v.z - mu) * inv * gg.z + bb.z;
    o.w = (v.w - mu) * inv * gg.w + bb.w;
    ((float4*)(out + (size_t)row * DMODEL))[tid] = o;
}

// ---------------- tf32 tensor-core NT GEMM ---------------------------------
// C[M,N] = A[M,K] * B[N,K]^T (+bias, +relu-then-res).
// Block tile 128x128, BK=32, 256 threads = 8 warps in 2(M) x 4(N), warp tile 64x32.
// mma.sync.m16n8k8 tf32. smem XOR-swizzled (16B-chunk ^ row&7).
template<bool RELU, bool RES>
__global__ __launch_bounds__(256) void gemm_tc(
    const float* __restrict__ A, const float* __restrict__ B,
    const float* __restrict__ bias, const float* __restrict__ res,
    float* __restrict__ C, int M, int N, int K)
{
    __shared__ uint32_t As[128*32];
    __shared__ uint32_t Bs[128*32];
    const int t = threadIdx.x;
    const int warp = t >> 5, lane = t & 31;
    const int wm = (warp >> 2) * 64;   // 0 / 64
    const int wn = (warp & 3) * 32;    // 0..96
    const int bm = blockIdx.y * 128, bn = blockIdx.x * 128;

    uint32_t sA = (uint32_t)__cvta_generic_to_shared(As);
    uint32_t sB = (uint32_t)__cvta_generic_to_shared(Bs);

    float acc[4][4][4];
    #pragma unroll
    for (int mt = 0; mt < 4; mt++)
        #pragma unroll
        for (int nt = 0; nt < 4; nt++)
            #pragma unroll
            for (int i = 0; i < 4; i++) acc[mt][nt][i] = 0.f;

    float4 pa[4], pb[4];
    // prefetch first slab
    #pragma unroll
    for (int i = 0; i < 4; i++) {
        int f = i * 256 + t;
        int r = f >> 3, c4 = f & 7;
        pa[i] = *(const float4*)(A + (size_t)(bm + r) * K + c4 * 4);
        pb[i] = *(const float4*)(B + (size_t)(bn + r) * K + c4 * 4);
    }

    for (int k0 = 0; k0 < K; k0 += 32) {
        // store slab (tf32-rounded, XOR swizzle)
        #pragma unroll
        for (int i = 0; i < 4; i++) {
            int f = i * 256 + t;
            int r = f >> 3, c4 = f & 7;
            int ch = c4 ^ (r & 7);
            uint32_t* da = &As[r * 32 + ch * 4];
            da[0] = f2tf(pa[i].x); da[1] = f2tf(pa[i].y);
            da[2] = f2tf(pa[i].z); da[3] = f2tf(pa[i].w);
            uint32_t* db = &Bs[r * 32 + ch * 4];
            db[0] = f2tf(pb[i].x); db[1] = f2tf(pb[i].y);
            db[2] = f2tf(pb[i].z); db[3] = f2tf(pb[i].w);
        }
        __syncthreads();
        // prefetch next slab
        if (k0 + 32 < K) {
            #pragma unroll
            for (int i = 0; i < 4; i++) {
                int f = i * 256 + t;
                int r = f >> 3, c4 = f & 7;
                pa[i] = *(const float4*)(A + (size_t)(bm + r) * K + k0 + 32 + c4 * 4);
                pb[i] = *(const float4*)(B + (size_t)(bn + r) * K + k0 + 32 + c4 * 4);
            }
        }
        // compute: 4 k-steps of 8
        #pragma unroll
        for (int ks2 = 0; ks2 < 2; ks2++) {
            uint32_t bfr[4][4];
            #pragma unroll
            for (int nt = 0; nt < 4; nt++) {
                int row  = wn + nt * 8 + (lane & 7);
                int kcol = ks2 * 16 + 4 * (lane >> 3);
                int ch   = (kcol >> 2) ^ (row & 7);
                ldsm4(bfr[nt], sB + (uint32_t)(row * 32 + ch * 4) * 4u);
            }
            #pragma unroll
            for (int kk = 0; kk < 2; kk++) {
                int ks = ks2 * 2 + kk;
                uint32_t afr[4][4];
                #pragma unroll
                for (int mt = 0; mt < 4; mt++) {
                    int row  = wm + mt * 16 + (lane & 15);
                    int kcol = ks * 8 + 4 * (lane >> 4);
                    int ch   = (kcol >> 2) ^ (row & 7);
                    ldsm4(afr[mt], sA + (uint32_t)(row * 32 + ch * 4) * 4u);
                }
                #pragma unroll
                for (int mt = 0; mt < 4; mt++)
                    #pragma unroll
                    for (int nt = 0; nt < 4; nt++)
                        mma_tf32(acc[mt][nt], afr[mt], bfr[nt][kk*2], bfr[nt][kk*2+1]);
            }
        }
        __syncthreads();
    }

    // epilogue: c-frag rows groupID(+8), cols 2*tig(+1)
    const int gr = lane >> 2, tg = lane & 3;
    #pragma unroll
    for (int mt = 0; mt < 4; mt++) {
        #pragma unroll
        for (int nt = 0; nt < 4; nt++) {
            int r0 = bm + wm + mt * 16 + gr;
            int c0 = bn + wn + nt * 8 + 2 * tg;
            float2 bval = {0.f, 0.f};
            if (bias) bval = *(const float2*)(bias + c0);
            #pragma unroll
            for (int half = 0; half < 2; half++) {
                int r = r0 + half * 8;
                float o0 = acc[mt][nt][half*2+0] + bval.x;
                float o1 = acc[mt][nt][half*2+1] + bval.y;
                if (RELU) { o0 = fmaxf(o0, 0.f); o1 = fmaxf(o1, 0.f); }
                if (RES) {
                    float2 rv = *(const float2*)(res + (size_t)r * N + c0);
                    o0 += rv.x; o1 += rv.y;
                }
                float2 ov = {o0, o1};
                *(float2*)(C + (size_t)r * N + c0) = ov;
            }
        }
    }
}

// ---------------- Flash attention: 64q x 64kv tiles, dk=64 -----------------
__global__ __launch_bounds__(256) void attn_k(
    const float* __restrict__ Q, const float* __restrict__ K,
    const float* __restrict__ V, const unsigned char* __restrict__ mask,
    float* __restrict__ O)
{
    __shared__ float Qt [64][64];
    __shared__ float KPs[64][64];
    __shared__ float Vs [64][64];
    int t  = threadIdx.x;
    int tx = t & 15, ty = t >> 4;
    int bh = blockIdx.y;
    int b = bh >> 4, h = bh & 15;
    int q0 = blockIdx.x * 64;
    size_t baseQ  = ((size_t)(b*SEQ + q0)) * DMODEL + h*DKH;
    size_t baseKV = ((size_t)(b*SEQ)) * DMODEL + h*DKH;
    const unsigned char* mrow = mask + (size_t)b * SEQ;

    {
        int r = t >> 2;
        int dbase = (t & 3) << 4;
        const float* qp = Q + baseQ + (size_t)r * DMODEL + dbase;
        #pragma unroll
        for (int i = 0; i < 4; i++) {
            float4 qv = *(const float4*)(qp + i*4);
            Qt[dbase+i*4+0][r] = qv.x; Qt[dbase+i*4+1][r] = qv.y;
            Qt[dbase+i*4+2][r] = qv.z; Qt[dbase+i*4+3][r] = qv.w;
        }
    }

    float m_[4], l_[4], o_[4][4];
    #pragma unroll
    for (int i = 0; i < 4; i++) {
        m_[i] = -INFINITY; l_[i] = 0.f;
        #pragma unroll
        for (int j = 0; j < 4; j++) o_[i][j] = 0.f;
    }

    for (int kv0 = 0; kv0 < SEQ; kv0 += 64) {
        __syncthreads();
        {
            int r = t >> 2;
            int dbase = (t & 3) << 4;
            const float* kp = K + baseKV + (size_t)(kv0 + r) * DMODEL + dbase;
            const float* vp = V + baseKV + (size_t)(kv0 + r) * DMODEL + dbase;
            #pragma unroll
            for (int i = 0; i < 4; i++) {
                float4 kv = *(const float4*)(kp + i*4);
                KPs[dbase+i*4+0][r] = kv.x; KPs[dbase+i*4+1][r] = kv.y;
                KPs[dbase+i*4+2][r] = kv.z; KPs[dbase+i*4+3][r] = kv.w;
                float4 vv = *(const float4*)(vp + i*4);
                *(float4*)&Vs[r][dbase+i*4] = vv;
            }
        }
        __syncthreads();

        float s[4][4];
        #pragma unroll
        for (int i = 0; i < 4; i++)
            #pragma unroll
            for (int j = 0; j < 4; j++) s[i][j] = 0.f;
        #pragma unroll 8
        for (int d = 0; d < 64; d++) {
            float4 qv = *(const float4*)&Qt[d][ty*4];
            float4 kv = *(const float4*)&KPs[d][tx*4];
            float qa[4] = {qv.x, qv.y, qv.z, qv.w};
            float ka[4] = {kv.x, kv.y, kv.z, kv.w};
            #pragma unroll
            for (int i = 0; i < 4; i++)
                #pragma unroll
                for (int j = 0; j < 4; j++)
                    s[i][j] += qa[i] * ka[j];
        }
        #pragma unroll
        for (int j = 0; j < 4; j++) {
            unsigned char mk = mrow[kv0 + tx*4 + j];
            #pragma unroll
            for (int i = 0; i < 4; i++)
                s[i][j] = mk ? -1e30f : s[i][j] * 0.125f;
        }
        float p[4][4];
        #pragma unroll
        for (int i = 0; i < 4; i++) {
            float rm = fmaxf(fmaxf(s[i][0], s[i][1]), fmaxf(s[i][2], s[i][3]));
            #pragma unroll
            for (int off = 8; off >= 1; off >>= 1)
                rm = fmaxf(rm, __shfl_xor_sync(0xffffffffu, rm, off));
            float mn = fmaxf(m_[i], rm);
            float corr = __expf(m_[i] - mn);
            m_[i] = mn;
            float rs = 0.f;
            #pragma unroll
            for (int j = 0; j < 4; j++) {
                p[i][j] = __expf(s[i][j] - mn);
                rs += p[i][j];
            }
            #pragma unroll
            for (int off = 8; off >= 1; off >>= 1)
                rs += __shfl_xor_sync(0xffffffffu, rs, off);
            l_[i] = l_[i] * corr + rs;
            #pragma unroll
            for (int j = 0; j < 4; j++) o_[i][j] *= corr;
        }
        __syncthreads();
        #pragma unroll
        for (int i = 0; i < 4; i++)
            #pragma unroll
            for (int j = 0; j < 4; j++)
                KPs[ty*4 + i][tx*4 + j] = p[i][j];
        __syncthreads();
        #pragma unroll 4
        for (int c4 = 0; c4 < 16; c4++) {
            float pr[4][4];
            #pragma unroll
            for (int i = 0; i < 4; i++)
                *(float4*)&pr[i][0] = *(const float4*)&KPs[ty*4 + i][c4*4];
            #pragma unroll
            for (int mcl = 0; mcl < 4; mcl++) {
                float4 vv = *(const float4*)&Vs[c4*4 + mcl][tx*4];
                float va[4] = {vv.x, vv.y, vv.z, vv.w};
                #pragma unroll
                for (int i = 0; i < 4; i++)
                    #pragma unroll
                    for (int j = 0; j < 4; j++)
                        o_[i][j] += pr[i][mcl] * va[j];
            }
        }
    }

    #pragma unroll
    for (int i = 0; i < 4; i++) {
        float invl = 1.f / l_[i];
        float4 ov = {o_[i][0]*invl, o_[i][1]*invl, o_[i][2]*invl, o_[i][3]*invl};
        float* op = O + ((size_t)(b*SEQ + q0 + ty*4 + i)) * DMODEL + h*DKH + tx*4;
        *(float4*)op = ov;
    }
}

// ---------------- driver -----------------------------------------------------
static float* sym_addr(const void* sym) {
    void* p = nullptr;
    cudaGetSymbolAddress(&p, sym);
    return (float*)p;
}

extern "C" void kernel_launch(void* const* d_in, const int* in_sizes, int n_in,
                              void* d_out, int out_size)
{
    const float*         x     = (const float*)d_in[0];
    const unsigned char* mask  = (const unsigned char*)d_in[1];
    const float*         W_Q   = (const float*)d_in[2];
    const float*         W_K   = (const float*)d_in[3];
    const float*         W_V   = (const float*)d_in[4];
    const float*         W_O   = (const float*)d_in[5];
    const float*         W1    = (const float*)d_in[6];
    const float*         b1    = (const float*)d_in[7];
    const float*         W2    = (const float*)d_in[8];
    const float*         b2    = (const float*)d_in[9];
    const float*         g1    = (const float*)d_in[10];
    const float*         beta1 = (const float*)d_in[11];
    const float*         g2    = (const float*)d_in[12];
    const float*         beta2 = (const float*)d_in[13];
    float* out = (float*)d_out;

    float* h  = sym_addr(g_h);
    float* q  = sym_addr(g_q);
    float* k  = sym_addr(g_k);
    float* v  = sym_addr(g_v);
    float* a  = sym_addr(g_a);
    float* x2 = sym_addr(g_x2);
    float* f1 = sym_addr(g_f1);

    const int M = MROWS;
    dim3 blk(256);
    dim3 gD (DMODEL/128, M/128);   // N=1024
    dim3 gF (DFF/128,    M/128);   // N=4096

    // 1. LN1
    layernorm_k<<<M, blk>>>(x, g1, beta1, h);
    // 2. QKV projections (tf32 tensor cores)
    gemm_tc<false,false><<<gD, blk>>>(h, W_Q, nullptr, nullptr, q, M, DMODEL, DMODEL);
    gemm_tc<false,false><<<gD, blk>>>(h, W_K, nullptr, nullptr, k, M, DMODEL, DMODEL);
    gemm_tc<false,false><<<gD, blk>>>(h, W_V, nullptr, nullptr, v, M, DMODEL, DMODEL);
    // 3. Attention (fp32 SIMT)
    attn_k<<<dim3(SEQ/64, BATCH*NHEADS), blk>>>(q, k, v, mask, a);
    // 4. O projection + residual
    gemm_tc<false,true><<<gD, blk>>>(a, W_O, nullptr, x, x2, M, DMODEL, DMODEL);
    // 5. LN2
    layernorm_k<<<M, blk>>>(x2, g2, beta2, h);
    // 6. FFN1 (+bias)
    gemm_tc<false,false><<<gF, blk>>>(h, W1, b1, nullptr, f1, M, DFF, DMODEL);
    // 7. FFN2 (+bias, relu-then-residual)
    gemm_tc<true,true><<<gD, blk>>>(f1, W2, b2, x2, out, M, DMODEL, DFF);
}

// round 13
// speedup vs baseline: 3.2405x; 1.7482x over previous
#include <cuda_runtime.h>
#include <math.h>
#include <stdint.h>

// Problem constants (fixed by setup_inputs)
#define DMODEL 1024
#define NHEADS 16
#define DKH    64
#define SEQ    2048
#define BATCH  2
#define MROWS  (BATCH*SEQ)   // 4096
#define DFF    4096

// ---------------- scratch (device globals: allocation-guard safe) ----------
__device__ float g_h [MROWS*DMODEL];
__device__ float g_q [MROWS*DMODEL];
__device__ float g_k [MROWS*DMODEL];
__device__ float g_v [MROWS*DMODEL];
__device__ float g_a [MROWS*DMODEL];
__device__ float g_x2[MROWS*DMODEL];
__device__ float g_f1[MROWS*DFF];

// ---------------- PTX helpers ----------------------------------------------
__device__ __forceinline__ uint32_t f2tf(float f) {
    uint32_t u;
    asm("cvt.rna.tf32.f32 %0, %1;" : "=r"(u) : "f"(f));
    return u;
}
__device__ __forceinline__ void ldsm4(uint32_t r[4], uint32_t addr) {
    asm volatile("ldmatrix.sync.aligned.m8n8.x4.shared.b16 {%0,%1,%2,%3}, [%4];"
                 : "=r"(r[0]), "=r"(r[1]), "=r"(r[2]), "=r"(r[3]) : "r"(addr));
}
__device__ __forceinline__ void mma_tf32(float c[4], const uint32_t a[4], uint32_t b0, uint32_t b1) {
    asm volatile("mma.sync.aligned.m16n8k8.row.col.f32.tf32.tf32.f32 "
                 "{%0,%1,%2,%3}, {%4,%5,%6,%7}, {%8,%9}, {%0,%1,%2,%3};"
                 : "+f"(c[0]), "+f"(c[1]), "+f"(c[2]), "+f"(c[3])
                 : "r"(a[0]), "r"(a[1]), "r"(a[2]), "r"(a[3]), "r"(b0), "r"(b1));
}

// ---------------- LayerNorm -------------------------------------------------
__global__ __launch_bounds__(256) void layernorm_k(
    const float* __restrict__ x, const float* __restrict__ gamma,
    const float* __restrict__ beta, float* __restrict__ out)
{
    int row = blockIdx.x;
    int tid = threadIdx.x;
    const float4* xr = (const float4*)(x + (size_t)row * DMODEL);
    float4 v = xr[tid];
    float s  = v.x + v.y + v.z + v.w;
    float ss = v.x*v.x + v.y*v.y + v.z*v.z + v.w*v.w;
    #pragma unroll
    for (int o = 16; o > 0; o >>= 1) {
        s  += __shfl_xor_sync(0xffffffffu, s,  o);
        ss += __shfl_xor_sync(0xffffffffu, ss, o);
    }
    __shared__ float sred[8], ssred[8];
    int w = tid >> 5;
    if ((tid & 31) == 0) { sred[w] = s; ssred[w] = ss; }
    __syncthreads();
    float tot = 0.f, tot2 = 0.f;
    #pragma unroll
    for (int i = 0; i < 8; i++) { tot += sred[i]; tot2 += ssred[i]; }
    float mu  = tot  * (1.0f / DMODEL);
    float var = tot2 * (1.0f / DMODEL) - mu * mu;
    float inv = rsqrtf(var + 1e-5f);
    float4 gg = ((const float4*)gamma)[tid];
    float4 bb = ((const float4*)beta)[tid];
    float4 o;
    o.x = (v.x - mu) * inv * gg.x + bb.x;
    o.y = (v.y - mu) * inv * gg.y + bb.y;
    o.z = (v.z - mu) * inv * gg.z + bb.z;
    o.w = (v.w - mu) * inv * gg.w + bb.w;
    ((float4*)(out + (size_t)row * DMODEL))[tid] = o;
}

// ---------------- tf32 TC NT GEMM, double-buffered BK=16 -------------------
// C[M,N] = A[M,K]*B[N,K]^T (+bias, +relu-then-res). 128x128 tile, 256 thr,
// 8 warps 2(M)x4(N), warp tile 64x32. Swizzle: ch = c4 ^ ((r>>1)&3).
template<bool RELU, bool RES>
__global__ __launch_bounds__(256) void gemm_tc(
    const float* __restrict__ A, const float* __restrict__ B,
    const float* __restrict__ bias, const float* __restrict__ res,
    float* __restrict__ C, int M, int N, int K)
{
    __shared__ __align__(16) uint32_t As[2][128*16];
    __shared__ __align__(16) uint32_t Bs[2][128*16];
    const int t = threadIdx.x;
    const int warp = t >> 5, lane = t & 31;
    const int wm = (warp >> 2) * 64;
    const int wn = (warp & 3) * 32;
    const int bm = blockIdx.y * 128, bn = blockIdx.x * 128;

    uint32_t sA = (uint32_t)__cvta_generic_to_shared(As);
    uint32_t sB = (uint32_t)__cvta_generic_to_shared(Bs);

    float acc[4][4][4];
    #pragma unroll
    for (int mt = 0; mt < 4; mt++)
        #pragma unroll
        for (int nt = 0; nt < 4; nt++)
            #pragma unroll
            for (int i = 0; i < 4; i++) acc[mt][nt][i] = 0.f;

    // loader: 2 float4 per matrix per stage. f = i*256+t -> r=f>>2, c4=f&3.
    const int r0l = t >> 2,        c0l = t & 3;
    const int r1l = (256 + t) >> 2, c1l = t & 3;   // +64 rows
    const int ch0 = c0l ^ ((r0l >> 1) & 3);
    const int ch1 = c1l ^ ((r1l >> 1) & 3);
    const int sidx0 = r0l * 16 + ch0 * 4;
    const int sidx1 = r1l * 16 + ch1 * 4;

    float4 pa0, pa1, pb0, pb1;
    pa0 = *(const float4*)(A + (size_t)(bm + r0l) * K + c0l * 4);
    pa1 = *(const float4*)(A + (size_t)(bm + r1l) * K + c1l * 4);
    pb0 = *(const float4*)(B + (size_t)(bn + r0l) * K + c0l * 4);
    pb1 = *(const float4*)(B + (size_t)(bn + r1l) * K + c1l * 4);

    // store stage 0
    {
        uint4 ua0 = {f2tf(pa0.x), f2tf(pa0.y), f2tf(pa0.z), f2tf(pa0.w)};
        uint4 ua1 = {f2tf(pa1.x), f2tf(pa1.y), f2tf(pa1.z), f2tf(pa1.w)};
        uint4 ub0 = {f2tf(pb0.x), f2tf(pb0.y), f2tf(pb0.z), f2tf(pb0.w)};
        uint4 ub1 = {f2tf(pb1.x), f2tf(pb1.y), f2tf(pb1.z), f2tf(pb1.w)};
        *(uint4*)&As[0][sidx0] = ua0; *(uint4*)&As[0][sidx1] = ua1;
        *(uint4*)&Bs[0][sidx0] = ub0; *(uint4*)&Bs[0][sidx1] = ub1;
    }
    __syncthreads();

    const int nstages = K >> 4;
    for (int s = 0; s < nstages; s++) {
        const int buf = s & 1;
        // prefetch next stage (global)
        if (s + 1 < nstages) {
            int ko = (s + 1) << 4;
            pa0 = *(const float4*)(A + (size_t)(bm + r0l) * K + ko + c0l * 4);
            pa1 = *(const float4*)(A + (size_t)(bm + r1l) * K + ko + c1l * 4);
            pb0 = *(const float4*)(B + (size_t)(bn + r0l) * K + ko + c0l * 4);
            pb1 = *(const float4*)(B + (size_t)(bn + r1l) * K + ko + c1l * 4);
        }
        // compute current stage
        uint32_t bufA = sA + (uint32_t)buf * (128*16*4);
        uint32_t bufB = sB + (uint32_t)buf * (128*16*4);
        uint32_t bfr[4][4];
        #pragma unroll
        for (int nt = 0; nt < 4; nt++) {
            int row = wn + nt * 8 + (lane & 7);
            int ch  = (lane >> 3) ^ ((row >> 1) & 3);
            ldsm4(bfr[nt], bufB + (uint32_t)(row * 16 + ch * 4) * 4u);
        }
        #pragma unroll
        for (int ks = 0; ks < 2; ks++) {
            uint32_t afr[4][4];
            #pragma unroll
            for (int mt = 0; mt < 4; mt++) {
                int row = wm + mt * 16 + (lane & 15);
                int ch  = (ks * 2 + (lane >> 4)) ^ ((row >> 1) & 3);
                ldsm4(afr[mt], bufA + (uint32_t)(row * 16 + ch * 4) * 4u);
            }
            #pragma unroll
            for (int mt = 0; mt < 4; mt++)
                #pragma unroll
                for (int nt = 0; nt < 4; nt++)
                    mma_tf32(acc[mt][nt], afr[mt], bfr[nt][ks*2], bfr[nt][ks*2+1]);
        }
        // store next stage
        if (s + 1 < nstages) {
            uint32_t* dA = &As[buf ^ 1][0];
            uint32_t* dB = &Bs[buf ^ 1][0];
            uint4 ua0 = {f2tf(pa0.x), f2tf(pa0.y), f2tf(pa0.z), f2tf(pa0.w)};
            uint4 ua1 = {f2tf(pa1.x), f2tf(pa1.y), f2tf(pa1.z), f2tf(pa1.w)};
            uint4 ub0 = {f2tf(pb0.x), f2tf(pb0.y), f2tf(pb0.z), f2tf(pb0.w)};
            uint4 ub1 = {f2tf(pb1.x), f2tf(pb1.y), f2tf(pb1.z), f2tf(pb1.w)};
            *(uint4*)&dA[sidx0] = ua0; *(uint4*)&dA[sidx1] = ua1;
            *(uint4*)&dB[sidx0] = ub0; *(uint4*)&dB[sidx1] = ub1;
        }
        __syncthreads();
    }

    // epilogue
    const int gr = lane >> 2, tg = lane & 3;
    #pragma unroll
    for (int mt = 0; mt < 4; mt++) {
        #pragma unroll
        for (int nt = 0; nt < 4; nt++) {
            int r0 = bm + wm + mt * 16 + gr;
            int c0 = bn + wn + nt * 8 + 2 * tg;
            float2 bval = {0.f, 0.f};
            if (bias) bval = *(const float2*)(bias + c0);
            #pragma unroll
            for (int half = 0; half < 2; half++) {
                int r = r0 + half * 8;
                float o0 = acc[mt][nt][half*2+0] + bval.x;
                float o1 = acc[mt][nt][half*2+1] + bval.y;
                if (RELU) { o0 = fmaxf(o0, 0.f); o1 = fmaxf(o1, 0.f); }
                if (RES) {
                    float2 rv = *(const float2*)(res + (size_t)r * N + c0);
                    o0 += rv.x; o1 += rv.y;
                }
                float2 ov = {o0, o1};
                *(float2*)(C + (size_t)r * N + c0) = ov;
            }
        }
    }
}

// ---------------- tf32 tensor-core flash attention -------------------------
// Block: 128 thr (4 warps), 64 q rows (16 per warp). KV tiles of 64. dk=64.
// K smem [kv][d] pad-68; V transposed smem [d][kv] pad-68 (both LDSM-clean).
// Q A-frags live in registers. P C->A frag conversion via quad shfls.
#define APAD 68
__global__ __launch_bounds__(128) void attn_tc(
    const float* __restrict__ Q, const float* __restrict__ K,
    const float* __restrict__ V, const unsigned char* __restrict__ mask,
    float* __restrict__ O)
{
    __shared__ __align__(16) uint32_t Ks[64*APAD];
    __shared__ __align__(16) uint32_t Vt[64*APAD];
    __shared__ unsigned char msk[64];

    const int t = threadIdx.x, warp = t >> 5, lane = t & 31;
    const int gr = lane >> 2, tg = lane & 3;
    const int b = blockIdx.y >> 4, h = blockIdx.y & 15;
    const int q0 = blockIdx.x * 64;
    const int qw = q0 + warp * 16;
    const size_t baseKV = ((size_t)(b * SEQ)) * DMODEL + h * DKH;

    uint32_t sK = (uint32_t)__cvta_generic_to_shared(Ks);
    uint32_t sV = (uint32_t)__cvta_generic_to_shared(Vt);

    // Q A-frags (rows qw+gr / qw+gr+8, k = d)
    uint32_t qa[8][4];
    {
        const float* Qb = Q + ((size_t)(b * SEQ + qw)) * DMODEL + h * DKH;
        const float* r0 = Qb + (size_t)gr * DMODEL;
        const float* r1 = Qb + (size_t)(gr + 8) * DMODEL;
        #pragma unroll
        for (int ks = 0; ks < 8; ks++) {
            qa[ks][0] = f2tf(r0[ks*8 + tg]);
            qa[ks][1] = f2tf(r1[ks*8 + tg]);
            qa[ks][2] = f2tf(r0[ks*8 + tg + 4]);
            qa[ks][3] = f2tf(r1[ks*8 + tg + 4]);
        }
    }

    float m0 = -INFINITY, m1 = -INFINITY, l0 = 0.f, l1 = 0.f;
    float oacc[8][4];
    #pragma unroll
    for (int i = 0; i < 8; i++)
        #pragma unroll
        for (int j = 0; j < 4; j++) oacc[i][j] = 0.f;

    const int ga = (lane >> 2) + ((warp & 1) << 3);   // d-group 0..15
    const int gb = (lane & 3) + ((warp >> 1) << 2);   // kv-group 0..7
    const int qb = lane & ~3;                         // quad base lane

    for (int kv0 = 0; kv0 < SEQ; kv0 += 64) {
        // ---- fill K [kv][d] ----
        {
            const float* Kg = K + baseKV + (size_t)kv0 * DMODEL;
            #pragma unroll
            for (int i = 0; i < 8; i++) {
                int idx = i * 128 + t;
                int r = idx >> 4, c4 = idx & 15;
                float4 kv4 = *(const float4*)(Kg + (size_t)r * DMODEL + c4 * 4);
                uint4 o = {f2tf(kv4.x), f2tf(kv4.y), f2tf(kv4.z), f2tf(kv4.w)};
                *(uint4*)&Ks[r * APAD + c4 * 4] = o;
            }
        }
        // ---- fill Vt [d][kv] via 4x4 register transpose ----
        {
            const float* Vg = V + baseKV + (size_t)kv0 * DMODEL;
            #pragma unroll
            for (int pass = 0; pass < 2; pass++) {
                int bb = gb + pass * 8;
                float4 vr[4];
                #pragma unroll
                for (int j = 0; j < 4; j++)
                    vr[j] = *(const float4*)(Vg + (size_t)(bb*4 + j) * DMODEL + ga * 4);
                const float* f0 = (const float*)&vr[0];
                const float* f1 = (const float*)&vr[1];
                const float* f2 = (const float*)&vr[2];
                const float* f3 = (const float*)&vr[3];
                #pragma unroll
                for (int i = 0; i < 4; i++) {
                    uint4 o = {f2tf(f0[i]), f2tf(f1[i]), f2tf(f2[i]), f2tf(f3[i])};
                    *(uint4*)&Vt[(ga*4 + i) * APAD + bb*4] = o;
                }
            }
        }
        if (t < 16)
            ((uint32_t*)msk)[t] = ((const uint32_t*)(mask + (size_t)b * SEQ + kv0))[t];
        __syncthreads();

        // ---- S = Q K^T (fp32 acc) ----
        float sc[8][4];
        #pragma unroll
        for (int nt = 0; nt < 8; nt++)
            #pragma unroll
            for (int j = 0; j < 4; j++) sc[nt][j] = 0.f;
        #pragma unroll
        for (int ks2 = 0; ks2 < 4; ks2++) {
            uint32_t kfr[8][4];
            #pragma unroll
            for (int nt = 0; nt < 8; nt++) {
                int row = nt * 8 + (lane & 7);
                int chunk = ks2 * 4 + (lane >> 3);
                ldsm4(kfr[nt], sK + (uint32_t)(row * APAD + chunk * 4) * 4u);
            }
            #pragma unroll
            for (int kk = 0; kk < 2; kk++) {
                int ks = ks2 * 2 + kk;
                #pragma unroll
                for (int nt = 0; nt < 8; nt++)
                    mma_tf32(sc[nt], qa[ks], kfr[nt][kk*2], kfr[nt][kk*2+1]);
            }
        }

        // ---- scale + mask ----
        #pragma unroll
        for (int nt = 0; nt < 8; nt++) {
            int c0 = nt * 8 + 2 * tg;
            bool ma = msk[c0] != 0, mb = msk[c0 + 1] != 0;
            sc[nt][0] = ma ? -1e30f : sc[nt][0] * 0.125f;
            sc[nt][1] = mb ? -1e30f : sc[nt][1] * 0.125f;
            sc[nt][2] = ma ? -1e30f : sc[nt][2] * 0.125f;
            sc[nt][3] = mb ? -1e30f : sc[nt][3] * 0.125f;
        }

        // ---- online softmax (rows gr and gr+8) ----
        float rm0 = -INFINITY, rm1 = -INFINITY;
        #pragma unroll
        for (int nt = 0; nt < 8; nt++) {
            rm0 = fmaxf(rm0, fmaxf(sc[nt][0], sc[nt][1]));
            rm1 = fmaxf(rm1, fmaxf(sc[nt][2], sc[nt][3]));
        }
        rm0 = fmaxf(rm0, __shfl_xor_sync(0xffffffffu, rm0, 1));
        rm0 = fmaxf(rm0, __shfl_xor_sync(0xffffffffu, rm0, 2));
        rm1 = fmaxf(rm1, __shfl_xor_sync(0xffffffffu, rm1, 1));
        rm1 = fmaxf(rm1, __shfl_xor_sync(0xffffffffu, rm1, 2));
        float mn0 = fmaxf(m0, rm0), mn1 = fmaxf(m1, rm1);
        float cr0 = __expf(m0 - mn0), cr1 = __expf(m1 - mn1);
        m0 = mn0; m1 = mn1;
        float rs0 = 0.f, rs1 = 0.f;
        #pragma unroll
        for (int nt = 0; nt < 8; nt++) {
            sc[nt][0] = __expf(sc[nt][0] - mn0);
            sc[nt][1] = __expf(sc[nt][1] - mn0);
            sc[nt][2] = __expf(sc[nt][2] - mn1);
            sc[nt][3] = __expf(sc[nt][3] - mn1);
            rs0 += sc[nt][0] + sc[nt][1];
            rs1 += sc[nt][2] + sc[nt][3];
        }
        rs0 += __shfl_xor_sync(0xffffffffu, rs0, 1);
        rs0 += __shfl_xor_sync(0xffffffffu, rs0, 2);
        rs1 += __shfl_xor_sync(0xffffffffu, rs1, 1);
        rs1 += __shfl_xor_sync(0xffffffffu, rs1, 2);
        l0 = l0 * cr0 + rs0;
        l1 = l1 * cr1 + rs1;
        #pragma unroll
        for (int nt = 0; nt < 8; nt++) {
            oacc[nt][0] *= cr0; oacc[nt][1] *= cr0;
            oacc[nt][2] *= cr1; oacc[nt][3] *= cr1;
        }

        // P -> tf32
        uint32_t pt[8][4];
        #pragma unroll
        for (int nt = 0; nt < 8; nt++)
            #pragma unroll
            for (int j = 0; j < 4; j++) pt[nt][j] = f2tf(sc[nt][j]);

        // ---- O += P V ----
        int sAl = qb + (tg >> 1), sBl = sAl + 2;
        bool odd = (tg & 1) != 0;
        #pragma unroll
        for (int ks2 = 0; ks2 < 4; ks2++) {
            uint32_t vfr[8][4];
            #pragma unroll
            for (int ntd = 0; ntd < 8; ntd++) {
                int row = ntd * 8 + (lane & 7);
                int chunk = ks2 * 4 + (lane >> 3);
                ldsm4(vfr[ntd], sV + (uint32_t)(row * APAD + chunk * 4) * 4u);
            }
            #pragma unroll
            for (int kk = 0; kk < 2; kk++) {
                int cnk = ks2 * 2 + kk;
                uint32_t x0 = __shfl_sync(0xffffffffu, pt[cnk][0], sAl);
                uint32_t x1 = __shfl_sync(0xffffffffu, pt[cnk][1], sAl);
                uint32_t x2 = __shfl_sync(0xffffffffu, pt[cnk][2], sAl);
                uint32_t x3 = __shfl_sync(0xffffffffu, pt[cnk][3], sAl);
                uint32_t y0 = __shfl_sync(0xffffffffu, pt[cnk][0], sBl);
                uint32_t y1 = __shfl_sync(0xffffffffu, pt[cnk][1], sBl);
                uint32_t y2 = __shfl_sync(0xffffffffu, pt[cnk][2], sBl);
                uint32_t y3 = __shfl_sync(0xffffffffu, pt[cnk][3], sBl);
                uint32_t af[4];
                af[0] = odd ? x1 : x0;
                af[1] = odd ? x3 : x2;
                af[2] = odd ? y1 : y0;
                af[3] = odd ? y3 : y2;
                #pragma unroll
                for (int ntd = 0; ntd < 8; ntd++)
                    mma_tf32(oacc[ntd], af, vfr[ntd][kk*2], vfr[ntd][kk*2+1]);
            }
        }
        __syncthreads();
    }

    // ---- epilogue ----
    float il0 = 1.f / l0, il1 = 1.f / l1;
    float* Ob = O + ((size_t)(b * SEQ + qw)) * DMODEL + h * DKH;
    #pragma unroll
    for (int ntd = 0; ntd < 8; ntd++) {
        int dc = ntd * 8 + 2 * tg;
        float2 o0 = {oacc[ntd][0] * il0, oacc[ntd][1] * il0};
        float2 o1 = {oacc[ntd][2] * il1, oacc[ntd][3] * il1};
        *(float2*)(Ob + (size_t)gr * DMODEL + dc) = o0;
        *(float2*)(Ob + (size_t)(gr + 8) * DMODEL + dc) = o1;
    }
}

// ---------------- driver -----------------------------------------------------
static float* sym_addr(const void* sym) {
    void* p = nullptr;
    cudaGetSymbolAddress(&p, sym);
    return (float*)p;
}

extern "C" void kernel_launch(void* const* d_in, const int* in_sizes, int n_in,
                              void* d_out, int out_size)
{
    const float*         x     = (const float*)d_in[0];
    const unsigned char* mask  = (const unsigned char*)d_in[1];
    const float*         W_Q   = (const float*)d_in[2];
    const float*         W_K   = (const float*)d_in[3];
    const float*         W_V   = (const float*)d_in[4];
    const float*         W_O   = (const float*)d_in[5];
    const float*         W1    = (const float*)d_in[6];
    const float*         b1    = (const float*)d_in[7];
    const float*         W2    = (const float*)d_in[8];
    const float*         b2    = (const float*)d_in[9];
    const float*         g1    = (const float*)d_in[10];
    const float*         beta1 = (const float*)d_in[11];
    const float*         g2    = (const float*)d_in[12];
    const float*         beta2 = (const float*)d_in[13];
    float* out = (float*)d_out;

    float* h  = sym_addr(g_h);
    float* q  = sym_addr(g_q);
    float* k  = sym_addr(g_k);
    float* v  = sym_addr(g_v);
    float* a  = sym_addr(g_a);
    float* x2 = sym_addr(g_x2);
    float* f1 = sym_addr(g_f1);

    const int M = MROWS;
    dim3 blk(256);
    dim3 gD (DMODEL/128, M/128);
    dim3 gF (DFF/128,    M/128);

    layernorm_k<<<M, blk>>>(x, g1, beta1, h);
    gemm_tc<false,false><<<gD, blk>>>(h, W_Q, nullptr, nullptr, q, M, DMODEL, DMODEL);
    gemm_tc<false,false><<<gD, blk>>>(h, W_K, nullptr, nullptr, k, M, DMODEL, DMODEL);
    gemm_tc<false,false><<<gD, blk>>>(h, W_V, nullptr, nullptr, v, M, DMODEL, DMODEL);
    attn_tc<<<dim3(SEQ/64, BATCH*NHEADS), 128>>>(q, k, v, mask, a);
    gemm_tc<false,true><<<gD, blk>>>(a, W_O, nullptr, x, x2, M, DMODEL, DMODEL);
    layernorm_k<<<M, blk>>>(x2, g2, beta2, h);
    gemm_tc<false,false><<<gF, blk>>>(h, W1, b1, nullptr, f1, M, DFF, DMODEL);
    gemm_tc<true,true><<<gD, blk>>>(f1, W2, b2, x2, out, M, DMODEL, DFF);
}